// round 7
// baseline (speedup 1.0000x reference)
#include <cuda_runtime.h>
#include <math.h>

// Problem constants
#define BB 64
#define TT 512
#define CC 384
#define HH 64

// Scratch for Q, K, V projections (8 MB each) — device globals, no allocation.
__device__ float g_q[BB * TT * HH];
__device__ float g_k[BB * TT * HH];
__device__ float g_v[BB * TT * HH];

// ---------------------------------------------------------------------------
// Projection kernel: out[m, h] = sum_c x[m, c] * W[c, h]
// M = B*T = 32768, K = 384, N = 64. Grid: (M/64, 3 weight matrices).
// Block 256 threads, 64x64 output tile, 4x4 register micro-tile per thread.
// ---------------------------------------------------------------------------
__global__ __launch_bounds__(256) void proj_kernel(
    const float* __restrict__ x,
    const float* __restrict__ Wq,
    const float* __restrict__ Wk,
    const float* __restrict__ Wv)
{
    __shared__ __align__(16) float As[64][33];   // x tile, padded
    __shared__ __align__(16) float Bs[32][64];   // W tile

    const int mt    = blockIdx.x;     // 0..511
    const int which = blockIdx.y;     // 0:Q 1:K 2:V
    const float* W  = (which == 0) ? Wq : (which == 1) ? Wk : Wv;
    float* outp     = (which == 0) ? g_q : (which == 1) ? g_k : g_v;

    const int tid = threadIdx.x;
    const int tx  = tid & 15;         // micro-tile col group
    const int ty  = tid >> 4;         // micro-tile row group
    const int m0  = mt * 64;

    float acc[4][4];
#pragma unroll
    for (int i = 0; i < 4; i++)
#pragma unroll
        for (int j = 0; j < 4; j++) acc[i][j] = 0.f;

    for (int k0 = 0; k0 < CC; k0 += 32) {
        // Load A tile 64x32 (coalesced)
        {
            const int c  = tid & 31;
            const int r0 = tid >> 5;
#pragma unroll
            for (int r = r0; r < 64; r += 8)
                As[r][c] = x[(size_t)(m0 + r) * CC + k0 + c];
        }
        // Load B tile 32x64 (coalesced)
        {
            const int c  = tid & 63;
            const int r0 = tid >> 6;
#pragma unroll
            for (int r = r0; r < 32; r += 4)
                Bs[r][c] = W[(k0 + r) * HH + c];
        }
        __syncthreads();

#pragma unroll
        for (int k = 0; k < 32; k++) {
            const float a0 = As[ty * 4 + 0][k];
            const float a1 = As[ty * 4 + 1][k];
            const float a2 = As[ty * 4 + 2][k];
            const float a3 = As[ty * 4 + 3][k];
            const float4 b = *(const float4*)&Bs[k][tx * 4];
            acc[0][0] += a0 * b.x; acc[0][1] += a0 * b.y; acc[0][2] += a0 * b.z; acc[0][3] += a0 * b.w;
            acc[1][0] += a1 * b.x; acc[1][1] += a1 * b.y; acc[1][2] += a1 * b.z; acc[1][3] += a1 * b.w;
            acc[2][0] += a2 * b.x; acc[2][1] += a2 * b.y; acc[2][2] += a2 * b.z; acc[2][3] += a2 * b.w;
            acc[3][0] += a3 * b.x; acc[3][1] += a3 * b.y; acc[3][2] += a3 * b.z; acc[3][3] += a3 * b.w;
        }
        __syncthreads();
    }

#pragma unroll
    for (int i = 0; i < 4; i++) {
        float4 r;
        r.x = acc[i][0]; r.y = acc[i][1]; r.z = acc[i][2]; r.w = acc[i][3];
        *(float4*)&outp[(size_t)(m0 + ty * 4 + i) * HH + tx * 4] = r;
    }
}

// ---------------------------------------------------------------------------
// Fused causal attention with online softmax (flash-attention style).
// Grid: (T/64 q-tiles, B). Block 256 threads.
// Per block: Q tile [64xH] resident (transposed in smem), loop over K/V tiles
// of 64 keys, skipping tiles strictly above the causal diagonal.
// Thread (ty, tx) owns a 4x4 tile: q rows ty*4+i, cols tx*4+j.
// ---------------------------------------------------------------------------
#define QT_STRIDE 68   // pad: keeps float4 16B-aligned, kills bank conflicts

__global__ __launch_bounds__(256) void attn_kernel(float* __restrict__ out)
{
    extern __shared__ __align__(16) float sm[];
    float (*Qt)[QT_STRIDE] = (float(*)[QT_STRIDE])sm;                       // [H][64] Q transposed
    float (*Kt)[QT_STRIDE] = (float(*)[QT_STRIDE])(sm + 64 * QT_STRIDE);    // [H][64] K transposed
    float (*Vs)[64]        = (float(*)[64])(sm + 2 * 64 * QT_STRIDE);       // [64][H] V natural
    float (*Ps)[QT_STRIDE] = (float(*)[QT_STRIDE])(sm + 2 * 64 * QT_STRIDE + 64 * 64); // [64][64] P

    const int qt  = (int)gridDim.x - 1 - (int)blockIdx.x;  // heavy tiles first
    const int b   = blockIdx.y;
    const int tid = threadIdx.x;
    const int tx  = tid & 15;
    const int ty  = tid >> 4;

    // Load Q tile transposed: Qt[h][r]
    {
        const float* qb = g_q + ((size_t)b * TT + qt * 64) * HH;
        const int c  = tid & 63;   // h
        const int r0 = tid >> 6;
#pragma unroll
        for (int r = r0; r < 64; r += 4)
            Qt[c][r] = qb[r * HH + c];
    }

    float m_i[4], l_i[4], o[4][4];
#pragma unroll
    for (int i = 0; i < 4; i++) {
        m_i[i] = -1e30f;
        l_i[i] = 0.f;
#pragma unroll
        for (int j = 0; j < 4; j++) o[i][j] = 0.f;
    }

    const float scale = 0.125f;   // 1/sqrt(64)

    for (int kt = 0; kt <= qt; kt++) {
        __syncthreads();  // prior PV done (and Q load done on iter 0) before overwriting tiles

        // Load K tile transposed, V tile natural
        {
            const float* kb = g_k + ((size_t)b * TT + kt * 64) * HH;
            const int c  = tid & 63;
            const int r0 = tid >> 6;
#pragma unroll
            for (int r = r0; r < 64; r += 4)
                Kt[c][r] = kb[r * HH + c];
        }
        {
            const float4* v4  = (const float4*)(g_v + ((size_t)b * TT + kt * 64) * HH);
            float4*       vs4 = (float4*)Vs;
#pragma unroll
            for (int i = tid; i < 64 * (HH / 4); i += 256) vs4[i] = v4[i];
        }
        __syncthreads();

        // S = Q K^T  (4x4 per thread)
        float s[4][4];
#pragma unroll
        for (int i = 0; i < 4; i++)
#pragma unroll
            for (int j = 0; j < 4; j++) s[i][j] = 0.f;

#pragma unroll 8
        for (int h = 0; h < HH; h++) {
            const float4 a = *(const float4*)&Qt[h][ty * 4];
            const float4 k4 = *(const float4*)&Kt[h][tx * 4];
            s[0][0] += a.x * k4.x; s[0][1] += a.x * k4.y; s[0][2] += a.x * k4.z; s[0][3] += a.x * k4.w;
            s[1][0] += a.y * k4.x; s[1][1] += a.y * k4.y; s[1][2] += a.y * k4.z; s[1][3] += a.y * k4.w;
            s[2][0] += a.z * k4.x; s[2][1] += a.z * k4.y; s[2][2] += a.z * k4.z; s[2][3] += a.z * k4.w;
            s[3][0] += a.w * k4.x; s[3][1] += a.w * k4.y; s[3][2] += a.w * k4.z; s[3][3] += a.w * k4.w;
        }

        // scale + causal mask (only the diagonal tile has masked entries)
#pragma unroll
        for (int i = 0; i < 4; i++)
#pragma unroll
            for (int j = 0; j < 4; j++) s[i][j] *= scale;

        if (kt == qt) {
#pragma unroll
            for (int i = 0; i < 4; i++)
#pragma unroll
                for (int j = 0; j < 4; j++)
                    if (tx * 4 + j > ty * 4 + i) s[i][j] = -1e30f;
        }

        // online softmax update per q row (row spread over 16 tx lanes)
#pragma unroll
        for (int i = 0; i < 4; i++) {
            float v = fmaxf(fmaxf(s[i][0], s[i][1]), fmaxf(s[i][2], s[i][3]));
#pragma unroll
            for (int off = 8; off >= 1; off >>= 1)
                v = fmaxf(v, __shfl_xor_sync(0xffffffffu, v, off));
            const float mnew  = fmaxf(m_i[i], v);
            const float alpha = __expf(m_i[i] - mnew);
            m_i[i] = mnew;

            float4 p;
            p.x = __expf(s[i][0] - mnew);
            p.y = __expf(s[i][1] - mnew);
            p.z = __expf(s[i][2] - mnew);
            p.w = __expf(s[i][3] - mnew);
            float rs = p.x + p.y + p.z + p.w;
#pragma unroll
            for (int off = 8; off >= 1; off >>= 1)
                rs += __shfl_xor_sync(0xffffffffu, rs, off);
            l_i[i] = l_i[i] * alpha + rs;

            *(float4*)&Ps[ty * 4 + i][tx * 4] = p;

            o[i][0] *= alpha; o[i][1] *= alpha; o[i][2] *= alpha; o[i][3] *= alpha;
        }
        __syncthreads();  // Ps visible to all before PV

        // O += P @ V
#pragma unroll 8
        for (int kv = 0; kv < 64; kv++) {
            const float a0 = Ps[ty * 4 + 0][kv];
            const float a1 = Ps[ty * 4 + 1][kv];
            const float a2 = Ps[ty * 4 + 2][kv];
            const float a3 = Ps[ty * 4 + 3][kv];
            const float4 v4 = *(const float4*)&Vs[kv][tx * 4];
            o[0][0] += a0 * v4.x; o[0][1] += a0 * v4.y; o[0][2] += a0 * v4.z; o[0][3] += a0 * v4.w;
            o[1][0] += a1 * v4.x; o[1][1] += a1 * v4.y; o[1][2] += a1 * v4.z; o[1][3] += a1 * v4.w;
            o[2][0] += a2 * v4.x; o[2][1] += a2 * v4.y; o[2][2] += a2 * v4.z; o[2][3] += a2 * v4.w;
            o[3][0] += a3 * v4.x; o[3][1] += a3 * v4.y; o[3][2] += a3 * v4.z; o[3][3] += a3 * v4.w;
        }
    }

    // epilogue: normalize and store
#pragma unroll
    for (int i = 0; i < 4; i++) {
        const float inv = 1.f / l_i[i];
        float4 r;
        r.x = o[i][0] * inv; r.y = o[i][1] * inv; r.z = o[i][2] * inv; r.w = o[i][3] * inv;
        *(float4*)&out[((size_t)b * TT + qt * 64 + ty * 4 + i) * HH + tx * 4] = r;
    }
}

// ---------------------------------------------------------------------------
// Launch
// ---------------------------------------------------------------------------
extern "C" void kernel_launch(void* const* d_in, const int* in_sizes, int n_in,
                              void* d_out, int out_size)
{
    const float* x  = (const float*)d_in[0];
    const float* Wq = (const float*)d_in[1];
    const float* Wk = (const float*)d_in[2];
    const float* Wv = (const float*)d_in[3];
    float* out = (float*)d_out;

    (void)in_sizes; (void)n_in; (void)out_size;

    // QKV projection
    {
        dim3 grid(BB * TT / 64, 3);
        proj_kernel<<<grid, 256>>>(x, Wq, Wk, Wv);
    }

    // Fused attention
    {
        const int smem_bytes = (2 * 64 * QT_STRIDE + 64 * 64 + 64 * QT_STRIDE) * (int)sizeof(float);
        cudaFuncSetAttribute(attn_kernel, cudaFuncAttributeMaxDynamicSharedMemorySize, smem_bytes);
        dim3 grid(TT / 64, BB);
        attn_kernel<<<grid, 256, smem_bytes>>>(out);
    }
}